// round 3
// baseline (speedup 1.0000x reference)
#include <cuda_runtime.h>
#include <cuda_fp16.h>
#include <cstdint>

// GPTQ int4 fused dequant + GEMM
//   out[M,N] = x[M,K] @ W[K,N],  W = scales[g] * (unpack4(qweight) - (unpack4(qzeros)+1))
// M=4096, K=4096, N=11008, GROUPSIZE=128, 8 int4 per int32.
//
// Round 2: harness stores fp16 tensors upcast to FLOAT32 (fp16 unsupported by
// harness dtype list). x/scales are float*, out is float*. Convert to fp16 at
// the SMEM boundary; GEMM runs fp16 mma.sync m16n8k16 with fp32 accum; output
// is rounded through fp16 then widened to float32 to match reference rounding.

#define M_DIM 4096
#define K_DIM 4096
#define N_DIM 11008
#define BM 128
#define BN 128
#define BK 32
#define NKT (K_DIM / BK)   // 128 k-tiles

__global__ __launch_bounds__(256, 1)
void gptq_gemm_kernel(const float* __restrict__ x,
                      const int*   __restrict__ qweight,
                      const float* __restrict__ scales,
                      const int*   __restrict__ qzeros,
                      float*       __restrict__ out)
{
    __shared__ __align__(16) __half As[2][BM][BK + 8];   // pad: conflict-free ldmatrix
    __shared__ __align__(16) __half Bs[2][BK][BN + 8];

    const int tid  = threadIdx.x;
    const int lane = tid & 31;
    const int warp = tid >> 5;
    const int wm   = warp >> 2;   // 0..1  (M dim)
    const int wn   = warp & 3;    // 0..3  (N dim)

    const int bm = blockIdx.y * BM;
    const int bn = blockIdx.x * BN;

    float acc[4][4][4];
#pragma unroll
    for (int i = 0; i < 4; i++)
#pragma unroll
        for (int j = 0; j < 4; j++)
#pragma unroll
            for (int r = 0; r < 4; r++) acc[i][j][r] = 0.f;

    // -------- global-load staging registers (for LDG/compute overlap) --------
    float4 a_stg[4];   // A tile: 128x32 floats, 256 thr -> 16 floats = 4x float4
    int    q_stg[2];
    int    z_stg[2];
    float  s_stg[2];

    // A mapping: chunk c in [0,1024): row = c/8, col = (c%8)*4 floats
    // B mapping: chunk c in [0,512):  kq = c/128 (0..3), n = c%128

    auto fetch = [&](int kt) {
        const int k0 = kt * BK;
#pragma unroll
        for (int it = 0; it < 4; it++) {
            int c   = tid + it * 256;
            int row = c >> 3;
            int col = (c & 7) << 2;
            a_stg[it] = *reinterpret_cast<const float4*>(
                &x[(size_t)(bm + row) * K_DIM + k0 + col]);
        }
        const int g = k0 >> 7;   // g_idx[k] = k / 128
#pragma unroll
        for (int it = 0; it < 2; it++) {
            int c  = tid + it * 256;
            int kq = c >> 7;
            int n  = c & 127;
            int gn = bn + n;
            q_stg[it] = qweight[(size_t)(k0 / 8 + kq) * N_DIM + gn];
            int zq    = qzeros[(size_t)g * (N_DIM / 8) + (gn >> 3)];
            z_stg[it] = ((zq >> ((gn & 7) * 4)) & 0xF) + 1;
            s_stg[it] = scales[(size_t)g * N_DIM + gn];
        }
    };

    auto commit = [&](int buf) {
#pragma unroll
        for (int it = 0; it < 4; it++) {
            int c   = tid + it * 256;
            int row = c >> 3;
            int col = (c & 7) << 2;
            __half2 h01 = __floats2half2_rn(a_stg[it].x, a_stg[it].y);
            __half2 h23 = __floats2half2_rn(a_stg[it].z, a_stg[it].w);
            *reinterpret_cast<__half2*>(&As[buf][row][col])     = h01;
            *reinterpret_cast<__half2*>(&As[buf][row][col + 2]) = h23;
        }
#pragma unroll
        for (int it = 0; it < 2; it++) {
            int c  = tid + it * 256;
            int kq = c >> 7;
            int n  = c & 127;
            int    q = q_stg[it];
            int    z = z_stg[it];
            __half s = __float2half_rn(s_stg[it]);   // lossless: value is fp16-exact
#pragma unroll
            for (int i = 0; i < 8; i++) {
                int w = ((q >> (4 * i)) & 0xF) - z;
                Bs[buf][kq * 8 + i][n] = __hmul(s, __int2half_rn(w));
            }
        }
    };

    auto compute = [&](int buf) {
#pragma unroll
        for (int ks = 0; ks < 2; ks++) {
            uint32_t a[4][4];
#pragma unroll
            for (int mt = 0; mt < 4; mt++) {
                const __half* p =
                    &As[buf][wm * 64 + mt * 16 + (lane & 15)][ks * 16 + (lane >> 4) * 8];
                uint32_t addr = (uint32_t)__cvta_generic_to_shared(p);
                asm volatile(
                    "ldmatrix.sync.aligned.m8n8.x4.shared.b16 {%0,%1,%2,%3}, [%4];"
                    : "=r"(a[mt][0]), "=r"(a[mt][1]), "=r"(a[mt][2]), "=r"(a[mt][3])
                    : "r"(addr));
            }
            uint32_t b[4][2];
#pragma unroll
            for (int ntp = 0; ntp < 2; ntp++) {
                const __half* p =
                    &Bs[buf][ks * 16 + (lane & 15)][wn * 32 + ntp * 16 + (lane >> 4) * 8];
                uint32_t addr = (uint32_t)__cvta_generic_to_shared(p);
                uint32_t r0, r1, r2, r3;
                asm volatile(
                    "ldmatrix.sync.aligned.m8n8.x4.trans.shared.b16 {%0,%1,%2,%3}, [%4];"
                    : "=r"(r0), "=r"(r1), "=r"(r2), "=r"(r3)
                    : "r"(addr));
                b[ntp * 2][0]     = r0;  // k0-7
                b[ntp * 2][1]     = r1;  // k8-15
                b[ntp * 2 + 1][0] = r2;
                b[ntp * 2 + 1][1] = r3;
            }
#pragma unroll
            for (int mt = 0; mt < 4; mt++)
#pragma unroll
                for (int nt = 0; nt < 4; nt++) {
                    asm volatile(
                        "mma.sync.aligned.m16n8k16.row.col.f32.f16.f16.f32 "
                        "{%0,%1,%2,%3}, {%4,%5,%6,%7}, {%8,%9}, {%0,%1,%2,%3};"
                        : "+f"(acc[mt][nt][0]), "+f"(acc[mt][nt][1]),
                          "+f"(acc[mt][nt][2]), "+f"(acc[mt][nt][3])
                        : "r"(a[mt][0]), "r"(a[mt][1]), "r"(a[mt][2]), "r"(a[mt][3]),
                          "r"(b[nt][0]), "r"(b[nt][1]));
                }
        }
    };

    // -------- mainloop: double-buffered --------
    fetch(0);
    commit(0);
    __syncthreads();

    for (int kt = 0; kt < NKT; kt++) {
        int buf = kt & 1;
        if (kt + 1 < NKT) fetch(kt + 1);      // LDGs overlap with mma below
        compute(buf);
        if (kt + 1 < NKT) commit(buf ^ 1);    // STS into the other buffer
        __syncthreads();
    }

    // -------- epilogue: round through fp16 (reference stores fp16) --------
#pragma unroll
    for (int mt = 0; mt < 4; mt++) {
        int row0 = bm + wm * 64 + mt * 16 + (lane >> 2);
#pragma unroll
        for (int nt = 0; nt < 4; nt++) {
            int col = bn + wn * 32 + nt * 8 + (lane & 3) * 2;
            float2 v0, v1;
            v0.x = __half2float(__float2half_rn(acc[mt][nt][0]));
            v0.y = __half2float(__float2half_rn(acc[mt][nt][1]));
            v1.x = __half2float(__float2half_rn(acc[mt][nt][2]));
            v1.y = __half2float(__float2half_rn(acc[mt][nt][3]));
            *reinterpret_cast<float2*>(&out[(size_t)row0 * N_DIM + col])       = v0;
            *reinterpret_cast<float2*>(&out[(size_t)(row0 + 8) * N_DIM + col]) = v1;
        }
    }
}

extern "C" void kernel_launch(void* const* d_in, const int* in_sizes, int n_in,
                              void* d_out, int out_size)
{
    // Identify inputs by element count — robust to metadata ordering.
    // x: 4096*4096 = 16777216 (fp16 upcast to float32)
    // qweight: 512*11008 = 5636096 (int32)
    // scales: 32*11008 = 352256 (fp16 upcast to float32)
    // qzeros: 32*1376 = 44032 (int32)
    // g_idx: 4096 (int32, unused: g = k/128)
    const float* x       = nullptr;
    const int*   qweight = nullptr;
    const float* scales  = nullptr;
    const int*   qzeros  = nullptr;

    for (int i = 0; i < n_in; i++) {
        switch (in_sizes[i]) {
            case 16777216: x       = (const float*)d_in[i]; break;
            case 5636096:  qweight = (const int*)  d_in[i]; break;
            case 352256:   scales  = (const float*)d_in[i]; break;
            case 44032:    qzeros  = (const int*)  d_in[i]; break;
            default: break;
        }
    }

    float* out = (float*)d_out;

    dim3 grid(N_DIM / BN, M_DIM / BM);   // (86, 32)
    dim3 block(256);
    gptq_gemm_kernel<<<grid, block>>>(x, qweight, scales, qzeros, out);
}

// round 7
// speedup vs baseline: 1.2677x; 1.2677x over previous
#include <cuda_runtime.h>
#include <cuda_fp16.h>
#include <cstdint>

// GPTQ int4 fused dequant + GEMM, sm_103 HMMA path (tcgen05 unavailable:
// harness compiles non-'a' target).
//   out[M,N] = x[M,K] @ W[K,N],  W = s[g] * (unpack4(qweight) - (unpack4(qzeros)+1))
// M=4096, K=4096, N=11008, GROUPSIZE=128. fp16 tensors arrive upcast to fp32.
//
// Kernel 0: x fp32 -> fp16 into __device__ buffer (enables cp.async A path).
// Kernel 1: 512 threads, BM=128 BN=128 BK=64, warp grid 4x4 (32x32 per warp),
//   3-stage cp.async A pipeline + triple-buffered B (LDG->dequant->STS.128,
//   n-major SMEM so B frags come from non-trans ldmatrix), mma.sync m16n8k16.

#define M_DIM 4096
#define K_DIM 4096
#define N_DIM 11008
#define BM 128
#define BN 128
#define BK 64
#define NKC (K_DIM / BK)    // 64 chunks
#define THREADS 512

// SMEM: 3 stages. A stage: 128 rows x 72 halves (pad 8) = 18432 B.
//        B stage: 128 n-rows x 72 halves (pad 8)        = 18432 B.
#define ROW_HALVES 72
#define A_STAGE (BM * ROW_HALVES * 2)
#define B_STAGE (BN * ROW_HALVES * 2)
#define SMEM_B_OFF (3 * A_STAGE)
#define SMEM_TOTAL (3 * (A_STAGE + B_STAGE))   // 110592 B

__device__ __half xh_g[(size_t)M_DIM * K_DIM];   // 32 MB fp16 copy of x

// ---------------- convert kernel ----------------
__global__ void convert_x_kernel(const float* __restrict__ x)
{
    size_t i = ((size_t)blockIdx.x * blockDim.x + threadIdx.x) * 8;
    float4 f0 = *reinterpret_cast<const float4*>(x + i);
    float4 f1 = *reinterpret_cast<const float4*>(x + i + 4);
    __half2 h0 = __floats2half2_rn(f0.x, f0.y);
    __half2 h1 = __floats2half2_rn(f0.z, f0.w);
    __half2 h2 = __floats2half2_rn(f1.x, f1.y);
    __half2 h3 = __floats2half2_rn(f1.z, f1.w);
    uint4 v;
    v.x = *reinterpret_cast<uint32_t*>(&h0);
    v.y = *reinterpret_cast<uint32_t*>(&h1);
    v.z = *reinterpret_cast<uint32_t*>(&h2);
    v.w = *reinterpret_cast<uint32_t*>(&h3);
    *reinterpret_cast<uint4*>(&xh_g[i]) = v;
}

// ---------------- helpers ----------------
__device__ __forceinline__ void cp_async16(void* dst_smem, const void* src) {
    uint32_t d = (uint32_t)__cvta_generic_to_shared(dst_smem);
    asm volatile("cp.async.cg.shared.global [%0], [%1], 16;" :: "r"(d), "l"(src) : "memory");
}
__device__ __forceinline__ void cp_commit() {
    asm volatile("cp.async.commit_group;" ::: "memory");
}
template <int N>
__device__ __forceinline__ void cp_wait() {
    asm volatile("cp.async.wait_group %0;" :: "n"(N) : "memory");
}

// ---------------- GEMM kernel ----------------
__global__ __launch_bounds__(THREADS, 1)
void gptq_gemm_kernel(const int*   __restrict__ qweight,
                      const float* __restrict__ scales,
                      const int*   __restrict__ qzeros,
                      float*       __restrict__ out)
{
    extern __shared__ char smem[];
    __half* As = reinterpret_cast<__half*>(smem);               // [3][128][72]
    __half* Bs = reinterpret_cast<__half*>(smem + SMEM_B_OFF);  // [3][128][72]

    const int tid  = threadIdx.x;
    const int lane = tid & 31;
    const int warp = tid >> 5;
    const int wm   = warp >> 2;   // 0..3 (32 rows each)
    const int wn   = warp & 3;    // 0..3 (32 cols each)
    const int bm   = blockIdx.y * BM;
    const int bn   = blockIdx.x * BN;

    float acc[2][4][4];
#pragma unroll
    for (int i = 0; i < 2; i++)
#pragma unroll
        for (int j = 0; j < 4; j++)
#pragma unroll
            for (int r = 0; r < 4; r++) acc[i][j][r] = 0.f;

    // ---- A cp.async mapping: 1024 16B-chunks per stage, 2 per thread ----
    // chunk cc: row = cc>>3, col8 = (cc&7)*8 halves
    auto issueA = [&](int c) {
        const int st = c % 3;
        __half* abase = As + (size_t)st * (A_STAGE / 2);
#pragma unroll
        for (int it = 0; it < 2; it++) {
            int cc  = tid + it * THREADS;
            int row = cc >> 3;
            int col = (cc & 7) << 3;
            cp_async16(abase + row * ROW_HALVES + col,
                       &xh_g[(size_t)(bm + row) * K_DIM + c * BK + col]);
        }
        cp_commit();
    };

    // ---- B staging: thread owns n = tid&127, kq = (tid>>7)*2 + {0,1} ----
    const int nloc = tid & 127;
    const int gn   = bn + nloc;
    const int kqh  = tid >> 7;        // 0..3
    int   qv[2];
    int   zz;
    float sf;

    auto fetchB = [&](int c) {
        const int g = c >> 1;         // group = (c*64)/128
        int zw = qzeros[(size_t)g * (N_DIM / 8) + (gn >> 3)];
        zz = ((zw >> ((gn & 7) * 4)) & 0xF) + 1;
        sf = scales[(size_t)g * N_DIM + gn];
#pragma unroll
        for (int w = 0; w < 2; w++)
            qv[w] = qweight[(size_t)(c * 8 + kqh * 2 + w) * N_DIM + gn];
    };

    auto storeB = [&](int c) {
        const int st = c % 3;
        __half* brow = Bs + (size_t)st * (B_STAGE / 2) + nloc * ROW_HALVES;
        const __half s = __float2half_rn(sf);
#pragma unroll
        for (int w = 0; w < 2; w++) {
            const int q = qv[w];
            __half h[8];
#pragma unroll
            for (int i = 0; i < 8; i++)
                h[i] = __hmul(s, __int2half_rn(((q >> (4 * i)) & 0xF) - zz));
            uint4 v;
            v.x = (uint32_t)*reinterpret_cast<uint16_t*>(&h[0]) | ((uint32_t)*reinterpret_cast<uint16_t*>(&h[1]) << 16);
            v.y = (uint32_t)*reinterpret_cast<uint16_t*>(&h[2]) | ((uint32_t)*reinterpret_cast<uint16_t*>(&h[3]) << 16);
            v.z = (uint32_t)*reinterpret_cast<uint16_t*>(&h[4]) | ((uint32_t)*reinterpret_cast<uint16_t*>(&h[5]) << 16);
            v.w = (uint32_t)*reinterpret_cast<uint16_t*>(&h[6]) | ((uint32_t)*reinterpret_cast<uint16_t*>(&h[7]) << 16);
            *reinterpret_cast<uint4*>(brow + (kqh * 2 + w) * 8) = v;
        }
    };

    auto compute = [&](int c) {
        const int st = c % 3;
        const __half* abase = As + (size_t)st * (A_STAGE / 2);
        const __half* bbase = Bs + (size_t)st * (B_STAGE / 2);
#pragma unroll
        for (int ks = 0; ks < 4; ks++) {
            uint32_t a[2][4];
#pragma unroll
            for (int mt = 0; mt < 2; mt++) {
                const __half* p = abase +
                    (wm * 32 + mt * 16 + (lane & 15)) * ROW_HALVES +
                    ks * 16 + (lane >> 4) * 8;
                uint32_t addr = (uint32_t)__cvta_generic_to_shared(p);
                asm volatile(
                    "ldmatrix.sync.aligned.m8n8.x4.shared.b16 {%0,%1,%2,%3}, [%4];"
                    : "=r"(a[mt][0]), "=r"(a[mt][1]), "=r"(a[mt][2]), "=r"(a[mt][3])
                    : "r"(addr));
            }
            uint32_t b[4][2];
#pragma unroll
            for (int ntp = 0; ntp < 2; ntp++) {
                // n-major B: non-trans ldmatrix. lane L: group g=L>>3,
                // n = wn*32 + ntp*16 + (g>>1)*8 + (L&7), k = ks*16 + (g&1)*8
                const __half* p = bbase +
                    (wn * 32 + ntp * 16 + ((lane >> 4) << 3) + (lane & 7)) * ROW_HALVES +
                    ks * 16 + (((lane >> 3) & 1) << 3);
                uint32_t addr = (uint32_t)__cvta_generic_to_shared(p);
                uint32_t r0, r1, r2, r3;
                asm volatile(
                    "ldmatrix.sync.aligned.m8n8.x4.shared.b16 {%0,%1,%2,%3}, [%4];"
                    : "=r"(r0), "=r"(r1), "=r"(r2), "=r"(r3)
                    : "r"(addr));
                b[ntp * 2][0]     = r0;
                b[ntp * 2][1]     = r1;
                b[ntp * 2 + 1][0] = r2;
                b[ntp * 2 + 1][1] = r3;
            }
#pragma unroll
            for (int mt = 0; mt < 2; mt++)
#pragma unroll
                for (int nt = 0; nt < 4; nt++) {
                    asm volatile(
                        "mma.sync.aligned.m16n8k16.row.col.f32.f16.f16.f32 "
                        "{%0,%1,%2,%3}, {%4,%5,%6,%7}, {%8,%9}, {%0,%1,%2,%3};"
                        : "+f"(acc[mt][nt][0]), "+f"(acc[mt][nt][1]),
                          "+f"(acc[mt][nt][2]), "+f"(acc[mt][nt][3])
                        : "r"(a[mt][0]), "r"(a[mt][1]), "r"(a[mt][2]), "r"(a[mt][3]),
                          "r"(b[nt][0]), "r"(b[nt][1]));
                }
        }
    };

    // -------- prologue --------
    fetchB(0);
    issueA(0);
    issueA(1);
    storeB(0);
    fetchB(1);
    cp_wait<1>();          // stage 0 A complete
    __syncthreads();

    // -------- mainloop --------
    for (int c = 0; c < NKC; ++c) {
        if (c + 1 < NKC) storeB(c + 1);     // into stage (c+1)%3 (free: readers were c-2)
        if (c + 2 < NKC) fetchB(c + 2);     // LDGs hidden under compute
        compute(c);
        if (c + 2 < NKC) { issueA(c + 2); cp_wait<1>(); }
        else             { cp_wait<0>(); }
        __syncthreads();
    }

    // -------- epilogue: round through fp16, store fp32 --------
#pragma unroll
    for (int mt = 0; mt < 2; mt++) {
        int row0 = bm + wm * 32 + mt * 16 + (lane >> 2);
#pragma unroll
        for (int nt = 0; nt < 4; nt++) {
            int col = bn + wn * 32 + nt * 8 + (lane & 3) * 2;
            float2 v0, v1;
            v0.x = __half2float(__float2half_rn(acc[mt][nt][0]));
            v0.y = __half2float(__float2half_rn(acc[mt][nt][1]));
            v1.x = __half2float(__float2half_rn(acc[mt][nt][2]));
            v1.y = __half2float(__float2half_rn(acc[mt][nt][3]));
            *reinterpret_cast<float2*>(&out[(size_t)row0 * N_DIM + col])       = v0;
            *reinterpret_cast<float2*>(&out[(size_t)(row0 + 8) * N_DIM + col]) = v1;
        }
    }
}

extern "C" void kernel_launch(void* const* d_in, const int* in_sizes, int n_in,
                              void* d_out, int out_size)
{
    // Identify inputs by element count (all distinct).
    const float* x       = nullptr;   // 16777216 (fp16 upcast to fp32)
    const int*   qweight = nullptr;   // 5636096
    const float* scales  = nullptr;   // 352256 (fp16 upcast to fp32)
    const int*   qzeros  = nullptr;   // 44032
    for (int i = 0; i < n_in; i++) {
        switch (in_sizes[i]) {
            case 16777216: x       = (const float*)d_in[i]; break;
            case 5636096:  qweight = (const int*)  d_in[i]; break;
            case 352256:   scales  = (const float*)d_in[i]; break;
            case 44032:    qzeros  = (const int*)  d_in[i]; break;
            default: break;
        }
    }
    float* out = (float*)d_out;

    // Kernel 0: fp32 -> fp16 convert of x (8 elems/thread)
    convert_x_kernel<<<(size_t)M_DIM * K_DIM / (256 * 8), 256>>>(x);

    // Kernel 1: fused dequant GEMM
    static bool attr_set = false;
    if (!attr_set) {
        cudaFuncSetAttribute(gptq_gemm_kernel,
                             cudaFuncAttributeMaxDynamicSharedMemorySize, SMEM_TOTAL);
        attr_set = true;
    }
    dim3 grid(N_DIM / BN, M_DIM / BM);   // (86, 32)
    gptq_gemm_kernel<<<grid, THREADS, SMEM_TOTAL>>>(qweight, scales, qzeros, out);
}

// round 12
// speedup vs baseline: 1.7824x; 1.4060x over previous
#include <cuda_runtime.h>
#include <cuda_fp16.h>
#include <cstdint>

// GPTQ int4 fused dequant + GEMM, sm_103 HMMA path.
//   out[M,N] = x[M,K] @ W[K,N],  W = s[g] * (unpack4(qweight) - (unpack4(qzeros)+1))
// M=4096, K=4096, N=11008, GROUPSIZE=128. fp16 tensors arrive upcast to fp32.
//
// Round 8: BM=128 BN=256 BK=64, 512 thr, warp grid 4x4 (32x64/warp) -> fewer
// LDSM per flop (smem-bound fix). Marlin-style int4->fp16 dequant via lop3
// magic + hsub2/hmul2 (exact), with matching k-permutation [0,4,1,5,2,6,3,7]
// applied to A in the fp32->fp16 convert kernel (dot product invariant).

#define M_DIM 4096
#define K_DIM 4096
#define N_DIM 11008
#define BM 128
#define BN 256
#define BK 64
#define NKC (K_DIM / BK)    // 64 chunks
#define THREADS 512

#define ROW_HALVES 72                       // 64 + 8 pad
#define A_STAGE (BM * ROW_HALVES * 2)       // 18432 B
#define B_STAGE (BN * ROW_HALVES * 2)       // 36864 B
#define SMEM_B_OFF (3 * A_STAGE)
#define SMEM_TOTAL (3 * (A_STAGE + B_STAGE))   // 165888 B

__device__ __half xh_g[(size_t)M_DIM * K_DIM];   // 32 MB fp16 copy of x (k-permuted)

// ---------------- convert kernel: fp32->fp16, k-perm [0,4,1,5,2,6,3,7] ----
__global__ void convert_x_kernel(const float* __restrict__ x)
{
    size_t i = ((size_t)blockIdx.x * blockDim.x + threadIdx.x) * 8;
    float4 f0 = *reinterpret_cast<const float4*>(x + i);      // k 0..3
    float4 f1 = *reinterpret_cast<const float4*>(x + i + 4);  // k 4..7
    __half2 h0 = __floats2half2_rn(f0.x, f1.x);   // pos 0,1 = k0,k4
    __half2 h1 = __floats2half2_rn(f0.y, f1.y);   // pos 2,3 = k1,k5
    __half2 h2 = __floats2half2_rn(f0.z, f1.z);   // pos 4,5 = k2,k6
    __half2 h3 = __floats2half2_rn(f0.w, f1.w);   // pos 6,7 = k3,k7
    uint4 v;
    v.x = *reinterpret_cast<uint32_t*>(&h0);
    v.y = *reinterpret_cast<uint32_t*>(&h1);
    v.z = *reinterpret_cast<uint32_t*>(&h2);
    v.w = *reinterpret_cast<uint32_t*>(&h3);
    *reinterpret_cast<uint4*>(&xh_g[i]) = v;
}

// ---------------- helpers ----------------
__device__ __forceinline__ void cp_async16(void* dst_smem, const void* src) {
    uint32_t d = (uint32_t)__cvta_generic_to_shared(dst_smem);
    asm volatile("cp.async.cg.shared.global [%0], [%1], 16;" :: "r"(d), "l"(src) : "memory");
}
__device__ __forceinline__ void cp_commit() {
    asm volatile("cp.async.commit_group;" ::: "memory");
}
template <int N>
__device__ __forceinline__ void cp_wait() {
    asm volatile("cp.async.wait_group %0;" :: "n"(N) : "memory");
}

// ---------------- GEMM kernel ----------------
__global__ __launch_bounds__(THREADS, 1)
void gptq_gemm_kernel(const int*   __restrict__ qweight,
                      const float* __restrict__ scales,
                      const int*   __restrict__ qzeros,
                      float*       __restrict__ out)
{
    extern __shared__ char smem[];
    __half* As = reinterpret_cast<__half*>(smem);               // [3][128][72]
    __half* Bs = reinterpret_cast<__half*>(smem + SMEM_B_OFF);  // [3][256][72]

    const int tid  = threadIdx.x;
    const int lane = tid & 31;
    const int warp = tid >> 5;
    const int wm   = warp >> 2;   // 0..3 (32 rows)
    const int wn   = warp & 3;    // 0..3 (64 cols)
    const int bm   = blockIdx.y * BM;
    const int bn   = blockIdx.x * BN;

    float acc[2][8][4];
#pragma unroll
    for (int i = 0; i < 2; i++)
#pragma unroll
        for (int j = 0; j < 8; j++)
#pragma unroll
            for (int r = 0; r < 4; r++) acc[i][j][r] = 0.f;

    // ---- A cp.async: 1024 16B-chunks/stage, 2 per thread ----
    auto issueA = [&](int c) {
        const int st = c % 3;
        __half* abase = As + (size_t)st * (A_STAGE / 2);
#pragma unroll
        for (int it = 0; it < 2; it++) {
            int cc  = tid + it * THREADS;
            int row = cc >> 3;
            int col = (cc & 7) << 3;
            cp_async16(abase + row * ROW_HALVES + col,
                       &xh_g[(size_t)(bm + row) * K_DIM + c * BK + col]);
        }
        cp_commit();
    };

    // ---- B staging: thread owns n = tid&255, words kq = (tid>>8)*4 + 0..3 ----
    const int nloc = tid & 255;
    const int gn   = bn + nloc;
    const int kqh  = tid >> 8;        // 0..1
    uint32_t qv[4];
    uint32_t z2;                      // half2(1024+z, 1024+z) bits
    uint32_t s2;                      // half2(s, s) bits

    auto fetchB = [&](int c) {
        const int g = c >> 1;         // group = (c*64)/128
        int zw = qzeros[(size_t)g * (N_DIM / 8) + (gn >> 3)];
        uint32_t zb = 0x6400u + (((uint32_t)(zw >> ((gn & 7) * 4)) & 0xF) + 1u);
        z2 = zb | (zb << 16);
        __half sh = __float2half_rn(scales[(size_t)g * N_DIM + gn]);
        uint32_t sb = (uint32_t)*reinterpret_cast<uint16_t*>(&sh);
        s2 = sb | (sb << 16);
#pragma unroll
        for (int w = 0; w < 4; w++)
            qv[w] = ((const uint32_t*)qweight)[(size_t)(c * 8 + kqh * 4 + w) * N_DIM + gn];
    };

    auto storeB = [&](int c) {
        const int st = c % 3;
        __half* brow = Bs + (size_t)st * (B_STAGE / 2) + nloc * ROW_HALVES;
        const __half2 zz = *reinterpret_cast<const __half2*>(&z2);
        const __half2 ss = *reinterpret_cast<const __half2*>(&s2);
#pragma unroll
        for (int w = 0; w < 4; w++) {
            const uint32_t q = qv[w];
            uint32_t t0 = ( q         & 0x000f000fu) | 0x64006400u;  // (v0, v4)+1024
            uint32_t t1 = ((q >> 4)   & 0x000f000fu) | 0x64006400u;  // (v1, v5)+1024
            uint32_t t2 = ((q >> 8)   & 0x000f000fu) | 0x64006400u;  // (v2, v6)+1024
            uint32_t t3 = ((q >> 12)  & 0x000f000fu) | 0x64006400u;  // (v3, v7)+1024
            __half2 p0 = __hmul2(__hsub2(*reinterpret_cast<__half2*>(&t0), zz), ss);
            __half2 p1 = __hmul2(__hsub2(*reinterpret_cast<__half2*>(&t1), zz), ss);
            __half2 p2 = __hmul2(__hsub2(*reinterpret_cast<__half2*>(&t2), zz), ss);
            __half2 p3 = __hmul2(__hsub2(*reinterpret_cast<__half2*>(&t3), zz), ss);
            uint4 v;
            v.x = *reinterpret_cast<uint32_t*>(&p0);
            v.y = *reinterpret_cast<uint32_t*>(&p1);
            v.z = *reinterpret_cast<uint32_t*>(&p2);
            v.w = *reinterpret_cast<uint32_t*>(&p3);
            *reinterpret_cast<uint4*>(brow + (kqh * 4 + w) * 8) = v;
        }
    };

    auto compute = [&](int c) {
        const int st = c % 3;
        const __half* abase = As + (size_t)st * (A_STAGE / 2);
        const __half* bbase = Bs + (size_t)st * (B_STAGE / 2);
#pragma unroll
        for (int ks = 0; ks < 4; ks++) {
            uint32_t a[2][4];
#pragma unroll
            for (int mt = 0; mt < 2; mt++) {
                const __half* p = abase +
                    (wm * 32 + mt * 16 + (lane & 15)) * ROW_HALVES +
                    ks * 16 + (lane >> 4) * 8;
                uint32_t addr = (uint32_t)__cvta_generic_to_shared(p);
                asm volatile(
                    "ldmatrix.sync.aligned.m8n8.x4.shared.b16 {%0,%1,%2,%3}, [%4];"
                    : "=r"(a[mt][0]), "=r"(a[mt][1]), "=r"(a[mt][2]), "=r"(a[mt][3])
                    : "r"(addr));
            }
#pragma unroll
            for (int np = 0; np < 4; np++) {   // 16 n-cols each
                const __half* p = bbase +
                    (wn * 64 + np * 16 + ((lane >> 4) << 3) + (lane & 7)) * ROW_HALVES +
                    ks * 16 + (((lane >> 3) & 1) << 3);
                uint32_t addr = (uint32_t)__cvta_generic_to_shared(p);
                uint32_t r0, r1, r2, r3;
                asm volatile(
                    "ldmatrix.sync.aligned.m8n8.x4.shared.b16 {%0,%1,%2,%3}, [%4];"
                    : "=r"(r0), "=r"(r1), "=r"(r2), "=r"(r3)
                    : "r"(addr));
#pragma unroll
                for (int mt = 0; mt < 2; mt++) {
                    asm volatile(
                        "mma.sync.aligned.m16n8k16.row.col.f32.f16.f16.f32 "
                        "{%0,%1,%2,%3}, {%4,%5,%6,%7}, {%8,%9}, {%0,%1,%2,%3};"
                        : "+f"(acc[mt][np*2][0]), "+f"(acc[mt][np*2][1]),
                          "+f"(acc[mt][np*2][2]), "+f"(acc[mt][np*2][3])
                        : "r"(a[mt][0]), "r"(a[mt][1]), "r"(a[mt][2]), "r"(a[mt][3]),
                          "r"(r0), "r"(r1));
                    asm volatile(
                        "mma.sync.aligned.m16n8k16.row.col.f32.f16.f16.f32 "
                        "{%0,%1,%2,%3}, {%4,%5,%6,%7}, {%8,%9}, {%0,%1,%2,%3};"
                        : "+f"(acc[mt][np*2+1][0]), "+f"(acc[mt][np*2+1][1]),
                          "+f"(acc[mt][np*2+1][2]), "+f"(acc[mt][np*2+1][3])
                        : "r"(a[mt][0]), "r"(a[mt][1]), "r"(a[mt][2]), "r"(a[mt][3]),
                          "r"(r2), "r"(r3));
                }
            }
        }
    };

    // -------- prologue --------
    fetchB(0);
    issueA(0);
    issueA(1);
    storeB(0);
    fetchB(1);
    cp_wait<1>();
    __syncthreads();

    // -------- mainloop --------
    for (int c = 0; c < NKC; ++c) {
        if (c + 1 < NKC) storeB(c + 1);
        if (c + 2 < NKC) fetchB(c + 2);
        compute(c);
        if (c + 2 < NKC) { issueA(c + 2); cp_wait<1>(); }
        else             { cp_wait<0>(); }
        __syncthreads();
    }

    // -------- epilogue: round through fp16, store fp32 --------
#pragma unroll
    for (int mt = 0; mt < 2; mt++) {
        int row0 = bm + wm * 32 + mt * 16 + (lane >> 2);
#pragma unroll
        for (int nt = 0; nt < 8; nt++) {
            int col = bn + wn * 64 + nt * 8 + (lane & 3) * 2;
            float2 v0, v1;
            v0.x = __half2float(__float2half_rn(acc[mt][nt][0]));
            v0.y = __half2float(__float2half_rn(acc[mt][nt][1]));
            v1.x = __half2float(__float2half_rn(acc[mt][nt][2]));
            v1.y = __half2float(__float2half_rn(acc[mt][nt][3]));
            *reinterpret_cast<float2*>(&out[(size_t)row0 * N_DIM + col])       = v0;
            *reinterpret_cast<float2*>(&out[(size_t)(row0 + 8) * N_DIM + col]) = v1;
        }
    }
}

extern "C" void kernel_launch(void* const* d_in, const int* in_sizes, int n_in,
                              void* d_out, int out_size)
{
    // Identify inputs by element count (all distinct).
    const float* x       = nullptr;   // 16777216 (fp16 upcast to fp32)
    const int*   qweight = nullptr;   // 5636096
    const float* scales  = nullptr;   // 352256 (fp16 upcast to fp32)
    const int*   qzeros  = nullptr;   // 44032
    for (int i = 0; i < n_in; i++) {
        switch (in_sizes[i]) {
            case 16777216: x       = (const float*)d_in[i]; break;
            case 5636096:  qweight = (const int*)  d_in[i]; break;
            case 352256:   scales  = (const float*)d_in[i]; break;
            case 44032:    qzeros  = (const int*)  d_in[i]; break;
            default: break;
        }
    }
    float* out = (float*)d_out;

    convert_x_kernel<<<(size_t)M_DIM * K_DIM / (256 * 8), 256>>>(x);

    static bool attr_set = false;
    if (!attr_set) {
        cudaFuncSetAttribute(gptq_gemm_kernel,
                             cudaFuncAttributeMaxDynamicSharedMemorySize, SMEM_TOTAL);
        attr_set = true;
    }
    dim3 grid(N_DIM / BN, M_DIM / BM);   // (43, 32)
    gptq_gemm_kernel<<<grid, THREADS, SMEM_TOTAL>>>(qweight, scales, qzeros, out);
}